// round 15
// baseline (speedup 1.0000x reference)
#include <cuda_runtime.h>
#include <cuda_bf16.h>
#include <cstdint>

// out[b, p*20+x, q*20+y] = (x!=y && p!=q) ? P[x,p]+Q[x,q]+Q[y,p]+P[y,q] : 0
//                          + (p==q && x==y) ? Mn[x,p] : 0
// P = F1 @ relu(L1) @ F2^T, Q = F1 @ relu(L2) @ F2^T, Mn = U1 @ U2^T.
//
// R15: batch-chunked pipeline. prep -> 4x (gemm_c -> pq_c) on the capture
// stream; each chunk's write_c runs on a second stream (event fork/join) so
// the drain-bound writer overlaps the remaining compute chunks.

#define NB 256
#define NN 20
#define DD 256
#define HI 10
#define MROWS (NB * NN)        // 5120
#define NCOLS (2 * DD)         // 512
#define MB16  (MROWS / 16)     // 320
#define KB16  (DD / 16)        // 16
#define NB16  (NCOLS / 16)     // 32
#define NCHUNK 4
#define BCH   (NB / NCHUNK)    // 64 batches per chunk
#define MBCH  (MB16 / NCHUNK)  // 80 m16-blocks per chunk

typedef unsigned long long ull;

// ---- device scratch ----
__device__ uint4 g_Ah[MB16 * KB16 * 32];
__device__ uint4 g_Al[MB16 * KB16 * 32];
__device__ uint4 g_Bh[NB16 * KB16 * 32];
__device__ uint4 g_Bl[NB16 * KB16 * 32];
__device__ float g_T[MROWS * NCOLS];
__device__ float g_scratch[NB * 1200];     // P[400] | Q[400] | Mn[400]

// ---- helpers ----
__device__ __forceinline__ uint32_t pk2(float x, float y) {
    __nv_bfloat162 v = __floats2bfloat162_rn(x, y);
    return *reinterpret_cast<uint32_t*>(&v);
}
__device__ __forceinline__ float bfhi(float x) {
    return __bfloat162float(__float2bfloat16_rn(x));
}

#define MMA_BF16(c, a, b0, b1)                                              \
    asm volatile("mma.sync.aligned.m16n8k16.row.col.f32.bf16.bf16.f32 "     \
        "{%0,%1,%2,%3}, {%4,%5,%6,%7}, {%8,%9}, {%0,%1,%2,%3};"             \
        : "+f"((c)[0]), "+f"((c)[1]), "+f"((c)[2]), "+f"((c)[3])            \
        : "r"((a).x), "r"((a).y), "r"((a).z), "r"((a).w), "r"(b0), "r"(b1))

#define FMA2(acc, x, y) \
    asm("fma.rn.f32x2 %0, %1, %2, %0;" : "+l"(acc) : "l"(x), "l"(y))
__device__ __forceinline__ float2 up64(ull v) {
    float2 r;
    asm("mov.b64 {%0,%1}, %2;" : "=f"(r.x), "=f"(r.y) : "l"(v));
    return r;
}

// ------------------------------------------------------------------- prep ---
__global__ void __launch_bounds__(256)
prep_kernel(const float* __restrict__ F1, const float* __restrict__ L1,
            const float* __restrict__ L2)
{
    const int tid = blockIdx.x * 256 + threadIdx.x;
    if (tid < MB16 * KB16 * 32) {
        const int lane = tid & 31;
        const int kb   = (tid >> 5) & 15;
        const int mb   = tid >> 9;
        const int g = lane >> 2, t = lane & 3;
        const float* r0 = F1 + (size_t)(mb * 16 + g) * DD + kb * 16;
        const float* r1 = r0 + 8 * DD;
        float2 f00 = *reinterpret_cast<const float2*>(r0 + 2 * t);
        float2 f01 = *reinterpret_cast<const float2*>(r0 + 8 + 2 * t);
        float2 f10 = *reinterpret_cast<const float2*>(r1 + 2 * t);
        float2 f11 = *reinterpret_cast<const float2*>(r1 + 8 + 2 * t);
        uint4 h, l;
        h.x = pk2(f00.x, f00.y);
        h.y = pk2(f10.x, f10.y);
        h.z = pk2(f01.x, f01.y);
        h.w = pk2(f11.x, f11.y);
        l.x = pk2(f00.x - bfhi(f00.x), f00.y - bfhi(f00.y));
        l.y = pk2(f10.x - bfhi(f10.x), f10.y - bfhi(f10.y));
        l.z = pk2(f01.x - bfhi(f01.x), f01.y - bfhi(f01.y));
        l.w = pk2(f11.x - bfhi(f11.x), f11.y - bfhi(f11.y));
        g_Ah[tid] = h;
        g_Al[tid] = l;
    } else {
        const int s    = tid - MB16 * KB16 * 32;
        const int lane = s & 31;
        const int kb   = (s >> 5) & 15;
        const int nb2  = s >> 9;
        const int g = lane >> 2, t = lane & 3;
        const int n0 = nb2 * 16 + g;
        const float* Ls = (n0 < DD) ? L1 : L2;
        const int nc  = (n0 < DD) ? n0 : n0 - DD;
        const int k0  = kb * 16;
        float w0a = fmaxf(Ls[(k0 + 2 * t)     * DD + nc], 0.f);
        float w0b = fmaxf(Ls[(k0 + 2 * t + 1) * DD + nc], 0.f);
        float w1a = fmaxf(Ls[(k0 + 8 + 2 * t) * DD + nc], 0.f);
        float w1b = fmaxf(Ls[(k0 + 9 + 2 * t) * DD + nc], 0.f);
        float w2a = fmaxf(Ls[(k0 + 2 * t)     * DD + nc + 8], 0.f);
        float w2b = fmaxf(Ls[(k0 + 2 * t + 1) * DD + nc + 8], 0.f);
        float w3a = fmaxf(Ls[(k0 + 8 + 2 * t) * DD + nc + 8], 0.f);
        float w3b = fmaxf(Ls[(k0 + 9 + 2 * t) * DD + nc + 8], 0.f);
        uint4 h, l;
        h.x = pk2(w0a, w0b);
        h.y = pk2(w1a, w1b);
        h.z = pk2(w2a, w2b);
        h.w = pk2(w3a, w3b);
        l.x = pk2(w0a - bfhi(w0a), w0b - bfhi(w0b));
        l.y = pk2(w1a - bfhi(w1a), w1b - bfhi(w1b));
        l.z = pk2(w2a - bfhi(w2a), w2b - bfhi(w2b));
        l.w = pk2(w3a - bfhi(w3a), w3b - bfhi(w3b));
        g_Bh[s] = h;
        g_Bl[s] = l;
    }
}

// ------------------------------------------------------------------- gemm ---
// per chunk: grid (8, MBCH/8=10), 256 threads; mb offset = chunk * MBCH.
__global__ void __launch_bounds__(256)
gemm_kernel(int mbOff)
{
    const int w    = threadIdx.x >> 5;
    const int lane = threadIdx.x & 31;
    const int mb   = mbOff + blockIdx.y * 8 + w;
    const int nb0  = blockIdx.x * 4;

    float c[8][4];
    #pragma unroll
    for (int nt = 0; nt < 8; nt++)
        #pragma unroll
        for (int v = 0; v < 4; v++) c[nt][v] = 0.f;

    const uint4* Ahp = g_Ah + (size_t)mb * KB16 * 32 + lane;
    const uint4* Alp = g_Al + (size_t)mb * KB16 * 32 + lane;

    uint4 ah = __ldcs(Ahp);
    uint4 al = __ldcs(Alp);

    #pragma unroll 1
    for (int kb = 0; kb < KB16; kb++) {
        uint4 bh[4], bl[4];
        #pragma unroll
        for (int j = 0; j < 4; j++) {
            bh[j] = g_Bh[((nb0 + j) * KB16 + kb) * 32 + lane];
            bl[j] = g_Bl[((nb0 + j) * KB16 + kb) * 32 + lane];
        }
        uint4 ahn = ah, aln = al;
        if (kb + 1 < KB16) {
            ahn = __ldcs(Ahp + (kb + 1) * 32);
            aln = __ldcs(Alp + (kb + 1) * 32);
        }
        #pragma unroll
        for (int j = 0; j < 4; j++) {
            MMA_BF16(c[2 * j],     ah, bh[j].x, bh[j].y);
            MMA_BF16(c[2 * j],     ah, bl[j].x, bl[j].y);
            MMA_BF16(c[2 * j],     al, bh[j].x, bh[j].y);
            MMA_BF16(c[2 * j + 1], ah, bh[j].z, bh[j].w);
            MMA_BF16(c[2 * j + 1], ah, bl[j].z, bl[j].w);
            MMA_BF16(c[2 * j + 1], al, bh[j].z, bh[j].w);
        }
        ah = ahn;
        al = aln;
    }

    const int g = lane >> 2, t = lane & 3;
    float* base0 = g_T + (size_t)(mb * 16 + g) * NCOLS + blockIdx.x * 64 + 2 * t;
    float* base1 = base0 + 8 * NCOLS;
    #pragma unroll
    for (int nt = 0; nt < 8; nt++) {
        *reinterpret_cast<float2*>(base0 + nt * 8) = make_float2(c[nt][0], c[nt][1]);
        *reinterpret_cast<float2*>(base1 + nt * 8) = make_float2(c[nt][2], c[nt][3]);
    }
}

// --------------------------------------------------------------------- pq ---
#define STRD 260
#define PQ_SMEM_FLOATS (10 * STRD * 2 + 20 * STRD)
#define PQ_SMEM_BYTES  (PQ_SMEM_FLOATS * 4)

__global__ void __launch_bounds__(256)
pq_kernel(const float* __restrict__ F2, const float* __restrict__ U1,
          const float* __restrict__ U2, int bOff)
{
    extern __shared__ float sm[];
    float* sT1 = sm;
    float* sT2 = sm + HI * STRD;
    float* sF  = sm + 2 * HI * STRD;

    const int hi = blockIdx.x;
    const int b  = bOff + blockIdx.y;
    const int t  = threadIdx.x;
    const int i0 = hi * HI;

    {
        const float4* Tv = reinterpret_cast<const float4*>(
            g_T + ((size_t)b * NN + i0) * NCOLS);
        #pragma unroll
        for (int i4 = t; i4 < HI * 128; i4 += 256) {
            int il = i4 >> 7, c = i4 & 127;
            float4 v = Tv[il * 128 + c];
            if (c < 64) *reinterpret_cast<float4*>(sT1 + il * STRD + c * 4) = v;
            else        *reinterpret_cast<float4*>(sT2 + il * STRD + (c - 64) * 4) = v;
        }
        const float4* f2v = reinterpret_cast<const float4*>(F2 + (size_t)b * NN * DD);
        #pragma unroll
        for (int i4 = t; i4 < NN * 64; i4 += 256) {
            int k = i4 >> 6, d4 = i4 & 63;
            *reinterpret_cast<float4*>(sF + k * STRD + d4 * 4) = f2v[i4];
        }
    }
    __syncthreads();

    {
        float* dst = g_scratch + b * 1200;
        #pragma unroll 1
        for (int idx = t; idx < 400; idx += 256) {
            int m = (idx >= 200) ? idx - 200 : idx;
            const float* Tb = (idx >= 200) ? sT2 : sT1;
            int il = m / NN, k = m - il * NN;
            const ulonglong2* Ti = reinterpret_cast<const ulonglong2*>(Tb + il * STRD);
            const ulonglong2* Fk = reinterpret_cast<const ulonglong2*>(sF + k * STRD);
            ull a0 = 0, a1 = 0, a2 = 0, a3 = 0;
            #pragma unroll
            for (int v = 0; v < DD / 4; v += 2) {
                ulonglong2 t0 = Ti[v], t1 = Ti[v + 1];
                ulonglong2 f0 = Fk[v], f1 = Fk[v + 1];
                FMA2(a0, t0.x, f0.x);
                FMA2(a1, t0.y, f0.y);
                FMA2(a2, t1.x, f1.x);
                FMA2(a3, t1.y, f1.y);
            }
            float2 s0 = up64(a0), s1 = up64(a1), s2 = up64(a2), s3 = up64(a3);
            float r = ((s0.x + s0.y) + (s1.x + s1.y)) + ((s2.x + s2.y) + (s3.x + s3.y));
            int off = (idx >= 200) ? 400 : 0;
            dst[off + (i0 + il) * NN + k] = r;
        }
    }
    __syncthreads();

    {
        const float4* u1v = reinterpret_cast<const float4*>(
            U1 + ((size_t)b * NN + i0) * DD);
        const float4* u2v = reinterpret_cast<const float4*>(U2 + (size_t)b * NN * DD);
        #pragma unroll
        for (int i4 = t; i4 < HI * 64; i4 += 256) {
            int il = i4 >> 6, d4 = i4 & 63;
            *reinterpret_cast<float4*>(sT1 + il * STRD + d4 * 4) = u1v[i4];
        }
        #pragma unroll
        for (int i4 = t; i4 < NN * 64; i4 += 256) {
            int k = i4 >> 6, d4 = i4 & 63;
            *reinterpret_cast<float4*>(sF + k * STRD + d4 * 4) = u2v[i4];
        }
    }
    __syncthreads();

    if (t < 200) {
        int il = t / NN, k = t - il * NN;
        const ulonglong2* Ui = reinterpret_cast<const ulonglong2*>(sT1 + il * STRD);
        const ulonglong2* Uk = reinterpret_cast<const ulonglong2*>(sF + k * STRD);
        ull m0 = 0, m1 = 0, m2 = 0, m3 = 0;
        #pragma unroll
        for (int v = 0; v < DD / 4; v += 2) {
            ulonglong2 uv0 = Ui[v], uv1 = Ui[v + 1];
            ulonglong2 kv0 = Uk[v], kv1 = Uk[v + 1];
            FMA2(m0, uv0.x, kv0.x);
            FMA2(m1, uv0.y, kv0.y);
            FMA2(m2, uv1.x, kv1.x);
            FMA2(m3, uv1.y, kv1.y);
        }
        float2 s0 = up64(m0), s1 = up64(m1), s2 = up64(m2), s3 = up64(m3);
        g_scratch[b * 1200 + 800 + (i0 + il) * NN + k] =
            ((s0.x + s0.y) + (s1.x + s1.y)) + ((s2.x + s2.y) + (s3.x + s3.y));
    }
}

// ------------------------------------------------------------------ write ---
__global__ void __launch_bounds__(512)
write_kernel(float* __restrict__ out, int bOff)
{
    __shared__ __align__(16) float sPT[NN * 24];
    __shared__ __align__(16) float sQT[NN * 24];
    __shared__ float sPd[NN * 21];
    __shared__ float sQd[NN * 21];
    __shared__ float sMnD[NN * 21];

    const int h = blockIdx.x;
    const int b = bOff + blockIdx.y;
    const int t = threadIdx.x;

    const float* s = g_scratch + (size_t)b * 1200;

    if (t < 400) {
        int i = t / NN, k = t - i * NN;
        float pv = s[t], qv = s[400 + t], mv = s[800 + t];
        sPd[i * 21 + k] = pv;
        sPT[k * 24 + i] = pv;
        sQd[i * 21 + k] = qv;
        sQT[k * 24 + i] = qv;
        sMnD[i * 21 + k] = mv;
    }
    __syncthreads();

    if (t < 500) {
        const int x0 = t / 100;
        const int cm = t - x0 * 100;
        const int q  = cm / 5;
        const int y0 = (cm - q * 5) * 4;

        const float4 pt = *reinterpret_cast<const float4*>(sPT + q * 24 + y0);
        int   xs[4];
        float c2[4];
        int   dxv[4];
        #pragma unroll
        for (int j = 0; j < 4; j++) {
            xs[j]  = x0 + 5 * j;
            c2[j]  = sQd[xs[j] * 21 + q];
            dxv[j] = xs[j] - y0;
        }

        float4* ob = reinterpret_cast<float4*>(out) + (size_t)b * 40000 + cm;

        #pragma unroll 2
        for (int pp = 0; pp < 10; pp++) {
            const int p = h * 10 + pp;
            const float4 qc = *reinterpret_cast<const float4*>(sQT + p * 24 + y0);
            const float bx = pt.x + qc.x, by = pt.y + qc.y;
            const float bz = pt.z + qc.z, bw = pt.w + qc.w;
            float4* obp = ob + p * 2000;

            if (q != p) {
                #pragma unroll
                for (int j = 0; j < 4; j++) {
                    const int x = xs[j];
                    const float c1 = sPd[x * 21 + p] + c2[j];
                    float4 v = make_float4(c1 + bx, c1 + by, c1 + bz, c1 + bw);
                    const int dx = dxv[j];
                    if (dx == 0) v.x = 0.f;
                    else if (dx == 1) v.y = 0.f;
                    else if (dx == 2) v.z = 0.f;
                    else if (dx == 3) v.w = 0.f;
                    __stcs(&obp[x * 100], v);
                }
            } else {
                #pragma unroll
                for (int j = 0; j < 4; j++) {
                    const int x = xs[j];
                    float4 v = make_float4(0.f, 0.f, 0.f, 0.f);
                    const float mn = sMnD[x * 21 + p];
                    const int dx = dxv[j];
                    if (dx == 0) v.x = mn;
                    else if (dx == 1) v.y = mn;
                    else if (dx == 2) v.z = mn;
                    else if (dx == 3) v.w = mn;
                    __stcs(&obp[x * 100], v);
                }
            }
        }
    }
}

// ----------------------------------------------------------------- launch ---
// Stream/events created once at static-init time (before the harness's
// memory baseline); per-call code only launches and records/waits events,
// which is graph-capture-legal (fork/join pattern).
static cudaStream_t g_s2;
static cudaEvent_t  g_evC[NCHUNK];
static cudaEvent_t  g_evJoin;
namespace {
struct StreamInit {
    StreamInit() {
        cudaStreamCreateWithFlags(&g_s2, cudaStreamNonBlocking);
        for (int i = 0; i < NCHUNK; i++)
            cudaEventCreateWithFlags(&g_evC[i], cudaEventDisableTiming);
        cudaEventCreateWithFlags(&g_evJoin, cudaEventDisableTiming);
    }
} g_streamInit;
}

extern "C" void kernel_launch(void* const* d_in, const int* in_sizes, int n_in,
                              void* d_out, int out_size)
{
    const float* Fs[4] = {nullptr, nullptr, nullptr, nullptr};
    const float* Ls[2] = {nullptr, nullptr};
    int nf = 0, nl = 0;
    for (int i = 0; i < n_in; i++) {
        if (in_sizes[i] == NB * NN * DD) {
            if (nf < 4) Fs[nf++] = (const float*)d_in[i];
        } else if (in_sizes[i] == DD * DD) {
            if (nl < 2) Ls[nl++] = (const float*)d_in[i];
        }
    }

    cudaFuncSetAttribute(pq_kernel,
                         cudaFuncAttributeMaxDynamicSharedMemorySize, PQ_SMEM_BYTES);

    const int prep_threads = MB16 * KB16 * 32 + NB16 * KB16 * 32;  // 180224
    prep_kernel<<<prep_threads / 256, 256>>>(Fs[0], Ls[0], Ls[1]);

    for (int c = 0; c < NCHUNK; c++) {
        gemm_kernel<<<dim3(8, MBCH / 8), 256>>>(c * MBCH);
        pq_kernel<<<dim3(2, BCH), 256, PQ_SMEM_BYTES>>>(Fs[1], Fs[2], Fs[3],
                                                        c * BCH);
        cudaEventRecord(g_evC[c], 0);
        cudaStreamWaitEvent(g_s2, g_evC[c], 0);
        write_kernel<<<dim3(2, BCH), 512, 0, g_s2>>>((float*)d_out, c * BCH);
    }
    cudaEventRecord(g_evJoin, g_s2);
    cudaStreamWaitEvent(0, g_evJoin, 0);
    (void)out_size;
}

// round 16
// speedup vs baseline: 1.5815x; 1.5815x over previous
#include <cuda_runtime.h>
#include <cuda_fp16.h>
#include <cstdint>

// out[b, p*20+x, q*20+y] = (x!=y && p!=q) ? P[x,p]+Q[x,q]+Q[y,p]+P[y,q] : 0
//                          + (p==q && x==y) ? Mn[x,p] : 0
// P = F1 @ relu(L1) @ F2^T, Q = F1 @ relu(L2) @ F2^T, Mn = U1 @ U2^T.
//
// R16: stage-1 GEMM via mma.sync m16n8k16 FP16, 2-pass split:
//   T = Ah @ (Bh + Bl),  A single-rounded fp16 (dropped (A-Ah)B ~ 2^-12).
// 33% fewer MMAs than the bf16 3-pass (R10-R14). Rest identical to R14.

#define NB 256
#define NN 20
#define DD 256
#define HI 10
#define MROWS (NB * NN)        // 5120
#define NCOLS (2 * DD)         // 512
#define MB16  (MROWS / 16)     // 320
#define KB16  (DD / 16)        // 16
#define NB16  (NCOLS / 16)     // 32

typedef unsigned long long ull;

// ---- device scratch ----
__device__ uint4 g_Ah[MB16 * KB16 * 32];   // A fragments, fp16 (single)
__device__ uint4 g_Bh[NB16 * KB16 * 32];   // B fragment pairs, fp16 hi
__device__ uint4 g_Bl[NB16 * KB16 * 32];   // fp16 lo
__device__ float g_T[MROWS * NCOLS];       // 10.5 MB
__device__ float g_scratch[NB * 1200];     // P[400] | Q[400] | Mn[400]

// ---- helpers ----
__device__ __forceinline__ uint32_t pk2h(float x, float y) {
    __half2 v = __floats2half2_rn(x, y);
    return *reinterpret_cast<uint32_t*>(&v);
}
__device__ __forceinline__ float hhi(float x) {
    return __half2float(__float2half_rn(x));
}

#define MMA_F16(c, a, b0, b1)                                               \
    asm volatile("mma.sync.aligned.m16n8k16.row.col.f32.f16.f16.f32 "       \
        "{%0,%1,%2,%3}, {%4,%5,%6,%7}, {%8,%9}, {%0,%1,%2,%3};"             \
        : "+f"((c)[0]), "+f"((c)[1]), "+f"((c)[2]), "+f"((c)[3])            \
        : "r"((a).x), "r"((a).y), "r"((a).z), "r"((a).w), "r"(b0), "r"(b1))

#define FMA2(acc, x, y) \
    asm("fma.rn.f32x2 %0, %1, %2, %0;" : "+l"(acc) : "l"(x), "l"(y))
__device__ __forceinline__ float2 up64(ull v) {
    float2 r;
    asm("mov.b64 {%0,%1}, %2;" : "=f"(r.x), "=f"(r.y) : "l"(v));
    return r;
}

// ------------------------------------------------------------------- prep ---
__global__ void __launch_bounds__(256)
prep_kernel(const float* __restrict__ F1, const float* __restrict__ L1,
            const float* __restrict__ L2)
{
    const int tid = blockIdx.x * 256 + threadIdx.x;
    if (tid < MB16 * KB16 * 32) {
        const int lane = tid & 31;
        const int kb   = (tid >> 5) & 15;
        const int mb   = tid >> 9;
        const int g = lane >> 2, t = lane & 3;
        const float* r0 = F1 + (size_t)(mb * 16 + g) * DD + kb * 16;
        const float* r1 = r0 + 8 * DD;
        float2 f00 = *reinterpret_cast<const float2*>(r0 + 2 * t);
        float2 f01 = *reinterpret_cast<const float2*>(r0 + 8 + 2 * t);
        float2 f10 = *reinterpret_cast<const float2*>(r1 + 2 * t);
        float2 f11 = *reinterpret_cast<const float2*>(r1 + 8 + 2 * t);
        uint4 h;
        h.x = pk2h(f00.x, f00.y);
        h.y = pk2h(f10.x, f10.y);
        h.z = pk2h(f01.x, f01.y);
        h.w = pk2h(f11.x, f11.y);
        g_Ah[tid] = h;
    } else {
        const int s    = tid - MB16 * KB16 * 32;
        const int lane = s & 31;
        const int kb   = (s >> 5) & 15;
        const int nb2  = s >> 9;
        const int g = lane >> 2, t = lane & 3;
        const int n0 = nb2 * 16 + g;
        const float* Ls = (n0 < DD) ? L1 : L2;
        const int nc  = (n0 < DD) ? n0 : n0 - DD;
        const int k0  = kb * 16;
        float w0a = fmaxf(Ls[(k0 + 2 * t)     * DD + nc], 0.f);
        float w0b = fmaxf(Ls[(k0 + 2 * t + 1) * DD + nc], 0.f);
        float w1a = fmaxf(Ls[(k0 + 8 + 2 * t) * DD + nc], 0.f);
        float w1b = fmaxf(Ls[(k0 + 9 + 2 * t) * DD + nc], 0.f);
        float w2a = fmaxf(Ls[(k0 + 2 * t)     * DD + nc + 8], 0.f);
        float w2b = fmaxf(Ls[(k0 + 2 * t + 1) * DD + nc + 8], 0.f);
        float w3a = fmaxf(Ls[(k0 + 8 + 2 * t) * DD + nc + 8], 0.f);
        float w3b = fmaxf(Ls[(k0 + 9 + 2 * t) * DD + nc + 8], 0.f);
        uint4 h, l;
        h.x = pk2h(w0a, w0b);
        h.y = pk2h(w1a, w1b);
        h.z = pk2h(w2a, w2b);
        h.w = pk2h(w3a, w3b);
        l.x = pk2h(w0a - hhi(w0a), w0b - hhi(w0b));
        l.y = pk2h(w1a - hhi(w1a), w1b - hhi(w1b));
        l.z = pk2h(w2a - hhi(w2a), w2b - hhi(w2b));
        l.w = pk2h(w3a - hhi(w3a), w3b - hhi(w3b));
        g_Bh[s] = h;
        g_Bl[s] = l;
    }
}

// ------------------------------------------------------------------- gemm ---
__global__ void __launch_bounds__(256)
gemm_kernel()
{
    const int w    = threadIdx.x >> 5;
    const int lane = threadIdx.x & 31;
    const int mb   = blockIdx.y * 8 + w;
    const int nb0  = blockIdx.x * 4;

    float c[8][4];
    #pragma unroll
    for (int nt = 0; nt < 8; nt++)
        #pragma unroll
        for (int v = 0; v < 4; v++) c[nt][v] = 0.f;

    const uint4* Ahp = g_Ah + (size_t)mb * KB16 * 32 + lane;
    uint4 ah = __ldcs(Ahp);

    #pragma unroll 1
    for (int kb = 0; kb < KB16; kb++) {
        uint4 bh[4], bl[4];
        #pragma unroll
        for (int j = 0; j < 4; j++) {
            bh[j] = g_Bh[((nb0 + j) * KB16 + kb) * 32 + lane];
            bl[j] = g_Bl[((nb0 + j) * KB16 + kb) * 32 + lane];
        }
        uint4 ahn = ah;
        if (kb + 1 < KB16) ahn = __ldcs(Ahp + (kb + 1) * 32);
        #pragma unroll
        for (int j = 0; j < 4; j++) {
            MMA_F16(c[2 * j],     ah, bh[j].x, bh[j].y);
            MMA_F16(c[2 * j],     ah, bl[j].x, bl[j].y);
            MMA_F16(c[2 * j + 1], ah, bh[j].z, bh[j].w);
            MMA_F16(c[2 * j + 1], ah, bl[j].z, bl[j].w);
        }
        ah = ahn;
    }

    const int g = lane >> 2, t = lane & 3;
    float* base0 = g_T + (size_t)(mb * 16 + g) * NCOLS + blockIdx.x * 64 + 2 * t;
    float* base1 = base0 + 8 * NCOLS;
    #pragma unroll
    for (int nt = 0; nt < 8; nt++) {
        *reinterpret_cast<float2*>(base0 + nt * 8) = make_float2(c[nt][0], c[nt][1]);
        *reinterpret_cast<float2*>(base1 + nt * 8) = make_float2(c[nt][2], c[nt][3]);
    }
}

// --------------------------------------------------------------------- pq ---
#define STRD 260
#define PQ_SMEM_FLOATS (10 * STRD * 2 + 20 * STRD)
#define PQ_SMEM_BYTES  (PQ_SMEM_FLOATS * 4)

__global__ void __launch_bounds__(256)
pq_kernel(const float* __restrict__ F2, const float* __restrict__ U1,
          const float* __restrict__ U2)
{
    extern __shared__ float sm[];
    float* sT1 = sm;
    float* sT2 = sm + HI * STRD;
    float* sF  = sm + 2 * HI * STRD;

    const int hi = blockIdx.x;
    const int b  = blockIdx.y;
    const int t  = threadIdx.x;
    const int i0 = hi * HI;

    {
        const float4* Tv = reinterpret_cast<const float4*>(
            g_T + ((size_t)b * NN + i0) * NCOLS);
        #pragma unroll
        for (int i4 = t; i4 < HI * 128; i4 += 256) {
            int il = i4 >> 7, c = i4 & 127;
            float4 v = Tv[il * 128 + c];
            if (c < 64) *reinterpret_cast<float4*>(sT1 + il * STRD + c * 4) = v;
            else        *reinterpret_cast<float4*>(sT2 + il * STRD + (c - 64) * 4) = v;
        }
        const float4* f2v = reinterpret_cast<const float4*>(F2 + (size_t)b * NN * DD);
        #pragma unroll
        for (int i4 = t; i4 < NN * 64; i4 += 256) {
            int k = i4 >> 6, d4 = i4 & 63;
            *reinterpret_cast<float4*>(sF + k * STRD + d4 * 4) = f2v[i4];
        }
    }
    __syncthreads();

    {
        float* dst = g_scratch + b * 1200;
        #pragma unroll 1
        for (int idx = t; idx < 400; idx += 256) {
            int m = (idx >= 200) ? idx - 200 : idx;
            const float* Tb = (idx >= 200) ? sT2 : sT1;
            int il = m / NN, k = m - il * NN;
            const ulonglong2* Ti = reinterpret_cast<const ulonglong2*>(Tb + il * STRD);
            const ulonglong2* Fk = reinterpret_cast<const ulonglong2*>(sF + k * STRD);
            ull a0 = 0, a1 = 0, a2 = 0, a3 = 0;
            #pragma unroll
            for (int v = 0; v < DD / 4; v += 2) {
                ulonglong2 t0 = Ti[v], t1 = Ti[v + 1];
                ulonglong2 f0 = Fk[v], f1 = Fk[v + 1];
                FMA2(a0, t0.x, f0.x);
                FMA2(a1, t0.y, f0.y);
                FMA2(a2, t1.x, f1.x);
                FMA2(a3, t1.y, f1.y);
            }
            float2 s0 = up64(a0), s1 = up64(a1), s2 = up64(a2), s3 = up64(a3);
            float r = ((s0.x + s0.y) + (s1.x + s1.y)) + ((s2.x + s2.y) + (s3.x + s3.y));
            int off = (idx >= 200) ? 400 : 0;
            dst[off + (i0 + il) * NN + k] = r;
        }
    }
    __syncthreads();

    {
        const float4* u1v = reinterpret_cast<const float4*>(
            U1 + ((size_t)b * NN + i0) * DD);
        const float4* u2v = reinterpret_cast<const float4*>(U2 + (size_t)b * NN * DD);
        #pragma unroll
        for (int i4 = t; i4 < HI * 64; i4 += 256) {
            int il = i4 >> 6, d4 = i4 & 63;
            *reinterpret_cast<float4*>(sT1 + il * STRD + d4 * 4) = u1v[i4];
        }
        #pragma unroll
        for (int i4 = t; i4 < NN * 64; i4 += 256) {
            int k = i4 >> 6, d4 = i4 & 63;
            *reinterpret_cast<float4*>(sF + k * STRD + d4 * 4) = u2v[i4];
        }
    }
    __syncthreads();

    if (t < 200) {
        int il = t / NN, k = t - il * NN;
        const ulonglong2* Ui = reinterpret_cast<const ulonglong2*>(sT1 + il * STRD);
        const ulonglong2* Uk = reinterpret_cast<const ulonglong2*>(sF + k * STRD);
        ull m0 = 0, m1 = 0, m2 = 0, m3 = 0;
        #pragma unroll
        for (int v = 0; v < DD / 4; v += 2) {
            ulonglong2 uv0 = Ui[v], uv1 = Ui[v + 1];
            ulonglong2 kv0 = Uk[v], kv1 = Uk[v + 1];
            FMA2(m0, uv0.x, kv0.x);
            FMA2(m1, uv0.y, kv0.y);
            FMA2(m2, uv1.x, kv1.x);
            FMA2(m3, uv1.y, kv1.y);
        }
        float2 s0 = up64(m0), s1 = up64(m1), s2 = up64(m2), s3 = up64(m3);
        g_scratch[b * 1200 + 800 + (i0 + il) * NN + k] =
            ((s0.x + s0.y) + (s1.x + s1.y)) + ((s2.x + s2.y) + (s3.x + s3.y));
    }
}

// ------------------------------------------------------------------ write ---
__global__ void __launch_bounds__(512)
write_kernel(float* __restrict__ out)
{
    __shared__ __align__(16) float sPT[NN * 24];
    __shared__ __align__(16) float sQT[NN * 24];
    __shared__ float sPd[NN * 21];
    __shared__ float sQd[NN * 21];
    __shared__ float sMnD[NN * 21];

    const int h = blockIdx.x;
    const int b = blockIdx.y;
    const int t = threadIdx.x;

    const float* s = g_scratch + (size_t)b * 1200;

    if (t < 400) {
        int i = t / NN, k = t - i * NN;
        float pv = s[t], qv = s[400 + t], mv = s[800 + t];
        sPd[i * 21 + k] = pv;
        sPT[k * 24 + i] = pv;
        sQd[i * 21 + k] = qv;
        sQT[k * 24 + i] = qv;
        sMnD[i * 21 + k] = mv;
    }
    __syncthreads();

    if (t < 500) {
        const int x0 = t / 100;
        const int cm = t - x0 * 100;
        const int q  = cm / 5;
        const int y0 = (cm - q * 5) * 4;

        const float4 pt = *reinterpret_cast<const float4*>(sPT + q * 24 + y0);
        int   xs[4];
        float c2[4];
        int   dxv[4];
        #pragma unroll
        for (int j = 0; j < 4; j++) {
            xs[j]  = x0 + 5 * j;
            c2[j]  = sQd[xs[j] * 21 + q];
            dxv[j] = xs[j] - y0;
        }

        float4* ob = reinterpret_cast<float4*>(out) + (size_t)b * 40000 + cm;

        #pragma unroll 2
        for (int pp = 0; pp < 10; pp++) {
            const int p = h * 10 + pp;
            const float4 qc = *reinterpret_cast<const float4*>(sQT + p * 24 + y0);
            const float bx = pt.x + qc.x, by = pt.y + qc.y;
            const float bz = pt.z + qc.z, bw = pt.w + qc.w;
            float4* obp = ob + p * 2000;

            if (q != p) {
                #pragma unroll
                for (int j = 0; j < 4; j++) {
                    const int x = xs[j];
                    const float c1 = sPd[x * 21 + p] + c2[j];
                    float4 v = make_float4(c1 + bx, c1 + by, c1 + bz, c1 + bw);
                    const int dx = dxv[j];
                    if (dx == 0) v.x = 0.f;
                    else if (dx == 1) v.y = 0.f;
                    else if (dx == 2) v.z = 0.f;
                    else if (dx == 3) v.w = 0.f;
                    __stcs(&obp[x * 100], v);
                }
            } else {
                #pragma unroll
                for (int j = 0; j < 4; j++) {
                    const int x = xs[j];
                    float4 v = make_float4(0.f, 0.f, 0.f, 0.f);
                    const float mn = sMnD[x * 21 + p];
                    const int dx = dxv[j];
                    if (dx == 0) v.x = mn;
                    else if (dx == 1) v.y = mn;
                    else if (dx == 2) v.z = mn;
                    else if (dx == 3) v.w = mn;
                    __stcs(&obp[x * 100], v);
                }
            }
        }
    }
}

// ----------------------------------------------------------------- launch ---
extern "C" void kernel_launch(void* const* d_in, const int* in_sizes, int n_in,
                              void* d_out, int out_size)
{
    const float* Fs[4] = {nullptr, nullptr, nullptr, nullptr};
    const float* Ls[2] = {nullptr, nullptr};
    int nf = 0, nl = 0;
    for (int i = 0; i < n_in; i++) {
        if (in_sizes[i] == NB * NN * DD) {
            if (nf < 4) Fs[nf++] = (const float*)d_in[i];
        } else if (in_sizes[i] == DD * DD) {
            if (nl < 2) Ls[nl++] = (const float*)d_in[i];
        }
    }

    cudaFuncSetAttribute(pq_kernel,
                         cudaFuncAttributeMaxDynamicSharedMemorySize, PQ_SMEM_BYTES);

    const int prep_threads = MB16 * KB16 * 32 + NB16 * KB16 * 32;  // 180224
    prep_kernel<<<prep_threads / 256, 256>>>(Fs[0], Ls[0], Ls[1]);
    gemm_kernel<<<dim3(8, 40), 256>>>();
    pq_kernel<<<dim3(2, NB), 256, PQ_SMEM_BYTES>>>(Fs[1], Fs[2], Fs[3]);
    write_kernel<<<dim3(2, NB), 512>>>((float*)d_out);
    (void)out_size;
}

// round 17
// speedup vs baseline: 1.7328x; 1.0956x over previous
#include <cuda_runtime.h>
#include <cuda_fp16.h>
#include <cstdint>

// out[b, p*20+x, q*20+y] = (x!=y && p!=q) ? P[x,p]+Q[x,q]+Q[y,p]+P[y,q] : 0
//                          + (p==q && x==y) ? Mn[x,p] : 0
// P = F1 @ relu(L1) @ F2^T, Q = F1 @ relu(L2) @ F2^T, Mn = U1 @ U2^T.
//
// R17: register-tiled pq. Thread computes a 2x2 (i,k) tile of BOTH P and Q
// (8 dots / 6 smem row-streams -> 0.75 KB LDS per dot vs 2.0 before); Mn
// 2x2-tiled. Cuts pq's smem crossbar traffic 614 MB -> ~256 MB.
// prep/gemm (fp16 2-pass HMMA) and write unchanged from R16.

#define NB 256
#define NN 20
#define DD 256
#define MROWS (NB * NN)        // 5120
#define NCOLS (2 * DD)         // 512
#define MB16  (MROWS / 16)     // 320
#define KB16  (DD / 16)        // 16
#define NB16  (NCOLS / 16)     // 32

typedef unsigned long long ull;

// ---- device scratch ----
__device__ uint4 g_Ah[MB16 * KB16 * 32];   // A fragments, fp16
__device__ uint4 g_Bh[NB16 * KB16 * 32];   // B fragment pairs, fp16 hi
__device__ uint4 g_Bl[NB16 * KB16 * 32];   // fp16 lo
__device__ float g_T[MROWS * NCOLS];       // 10.5 MB
__device__ float g_scratch[NB * 1200];     // P[400] | Q[400] | Mn[400]

// ---- helpers ----
__device__ __forceinline__ uint32_t pk2h(float x, float y) {
    __half2 v = __floats2half2_rn(x, y);
    return *reinterpret_cast<uint32_t*>(&v);
}
__device__ __forceinline__ float hhi(float x) {
    return __half2float(__float2half_rn(x));
}

#define MMA_F16(c, a, b0, b1)                                               \
    asm volatile("mma.sync.aligned.m16n8k16.row.col.f32.f16.f16.f32 "       \
        "{%0,%1,%2,%3}, {%4,%5,%6,%7}, {%8,%9}, {%0,%1,%2,%3};"             \
        : "+f"((c)[0]), "+f"((c)[1]), "+f"((c)[2]), "+f"((c)[3])            \
        : "r"((a).x), "r"((a).y), "r"((a).z), "r"((a).w), "r"(b0), "r"(b1))

#define FMA2(acc, x, y) \
    asm("fma.rn.f32x2 %0, %1, %2, %0;" : "+l"(acc) : "l"(x), "l"(y))
__device__ __forceinline__ float red64(ull v) {
    float2 r;
    asm("mov.b64 {%0,%1}, %2;" : "=f"(r.x), "=f"(r.y) : "l"(v));
    return r.x + r.y;
}

// ------------------------------------------------------------------- prep ---
__global__ void __launch_bounds__(256)
prep_kernel(const float* __restrict__ F1, const float* __restrict__ L1,
            const float* __restrict__ L2)
{
    const int tid = blockIdx.x * 256 + threadIdx.x;
    if (tid < MB16 * KB16 * 32) {
        const int lane = tid & 31;
        const int kb   = (tid >> 5) & 15;
        const int mb   = tid >> 9;
        const int g = lane >> 2, t = lane & 3;
        const float* r0 = F1 + (size_t)(mb * 16 + g) * DD + kb * 16;
        const float* r1 = r0 + 8 * DD;
        float2 f00 = *reinterpret_cast<const float2*>(r0 + 2 * t);
        float2 f01 = *reinterpret_cast<const float2*>(r0 + 8 + 2 * t);
        float2 f10 = *reinterpret_cast<const float2*>(r1 + 2 * t);
        float2 f11 = *reinterpret_cast<const float2*>(r1 + 8 + 2 * t);
        uint4 h;
        h.x = pk2h(f00.x, f00.y);
        h.y = pk2h(f10.x, f10.y);
        h.z = pk2h(f01.x, f01.y);
        h.w = pk2h(f11.x, f11.y);
        g_Ah[tid] = h;
    } else {
        const int s    = tid - MB16 * KB16 * 32;
        const int lane = s & 31;
        const int kb   = (s >> 5) & 15;
        const int nb2  = s >> 9;
        const int g = lane >> 2, t = lane & 3;
        const int n0 = nb2 * 16 + g;
        const float* Ls = (n0 < DD) ? L1 : L2;
        const int nc  = (n0 < DD) ? n0 : n0 - DD;
        const int k0  = kb * 16;
        float w0a = fmaxf(Ls[(k0 + 2 * t)     * DD + nc], 0.f);
        float w0b = fmaxf(Ls[(k0 + 2 * t + 1) * DD + nc], 0.f);
        float w1a = fmaxf(Ls[(k0 + 8 + 2 * t) * DD + nc], 0.f);
        float w1b = fmaxf(Ls[(k0 + 9 + 2 * t) * DD + nc], 0.f);
        float w2a = fmaxf(Ls[(k0 + 2 * t)     * DD + nc + 8], 0.f);
        float w2b = fmaxf(Ls[(k0 + 2 * t + 1) * DD + nc + 8], 0.f);
        float w3a = fmaxf(Ls[(k0 + 8 + 2 * t) * DD + nc + 8], 0.f);
        float w3b = fmaxf(Ls[(k0 + 9 + 2 * t) * DD + nc + 8], 0.f);
        uint4 h, l;
        h.x = pk2h(w0a, w0b);
        h.y = pk2h(w1a, w1b);
        h.z = pk2h(w2a, w2b);
        h.w = pk2h(w3a, w3b);
        l.x = pk2h(w0a - hhi(w0a), w0b - hhi(w0b));
        l.y = pk2h(w1a - hhi(w1a), w1b - hhi(w1b));
        l.z = pk2h(w2a - hhi(w2a), w2b - hhi(w2b));
        l.w = pk2h(w3a - hhi(w3a), w3b - hhi(w3b));
        g_Bh[s] = h;
        g_Bl[s] = l;
    }
}

// ------------------------------------------------------------------- gemm ---
__global__ void __launch_bounds__(256)
gemm_kernel()
{
    const int w    = threadIdx.x >> 5;
    const int lane = threadIdx.x & 31;
    const int mb   = blockIdx.y * 8 + w;
    const int nb0  = blockIdx.x * 4;

    float c[8][4];
    #pragma unroll
    for (int nt = 0; nt < 8; nt++)
        #pragma unroll
        for (int v = 0; v < 4; v++) c[nt][v] = 0.f;

    const uint4* Ahp = g_Ah + (size_t)mb * KB16 * 32 + lane;
    uint4 ah = __ldcs(Ahp);

    #pragma unroll 1
    for (int kb = 0; kb < KB16; kb++) {
        uint4 bh[4], bl[4];
        #pragma unroll
        for (int j = 0; j < 4; j++) {
            bh[j] = g_Bh[((nb0 + j) * KB16 + kb) * 32 + lane];
            bl[j] = g_Bl[((nb0 + j) * KB16 + kb) * 32 + lane];
        }
        uint4 ahn = ah;
        if (kb + 1 < KB16) ahn = __ldcs(Ahp + (kb + 1) * 32);
        #pragma unroll
        for (int j = 0; j < 4; j++) {
            MMA_F16(c[2 * j],     ah, bh[j].x, bh[j].y);
            MMA_F16(c[2 * j],     ah, bl[j].x, bl[j].y);
            MMA_F16(c[2 * j + 1], ah, bh[j].z, bh[j].w);
            MMA_F16(c[2 * j + 1], ah, bl[j].z, bl[j].w);
        }
        ah = ahn;
    }

    const int g = lane >> 2, t = lane & 3;
    float* base0 = g_T + (size_t)(mb * 16 + g) * NCOLS + blockIdx.x * 64 + 2 * t;
    float* base1 = base0 + 8 * NCOLS;
    #pragma unroll
    for (int nt = 0; nt < 8; nt++) {
        *reinterpret_cast<float2*>(base0 + nt * 8) = make_float2(c[nt][0], c[nt][1]);
        *reinterpret_cast<float2*>(base1 + nt * 8) = make_float2(c[nt][2], c[nt][3]);
    }
}

// --------------------------------------------------------------------- pq ---
// grid 256 (block = batch), 128 threads, register-tiled 2x2 dots.
#define STRD 260
#define PQ_SMEM_FLOATS (3 * NN * STRD)     // T1, T2, F2(->U2); 62.4 KB
#define PQ_SMEM_BYTES  (PQ_SMEM_FLOATS * 4)

__global__ void __launch_bounds__(128)
pq_kernel(const float* __restrict__ F2, const float* __restrict__ U1,
          const float* __restrict__ U2)
{
    extern __shared__ float sm[];
    float* sT1 = sm;                 // [20][260]: T1 ; later U1
    float* sT2 = sm + NN * STRD;     // [20][260]: T2
    float* sF  = sm + 2 * NN * STRD; // [20][260]: F2 ; later U2

    const int b = blockIdx.x;
    const int t = threadIdx.x;       // 0..127

    // ---- stage T (split halves) and F2 ----
    {
        const float4* Tv = reinterpret_cast<const float4*>(g_T + (size_t)b * NN * NCOLS);
        #pragma unroll
        for (int i4 = t; i4 < NN * 128; i4 += 128) {
            int i = i4 >> 7, c = i4 & 127;
            float4 v = Tv[i4];
            if (c < 64) *reinterpret_cast<float4*>(sT1 + i * STRD + c * 4) = v;
            else        *reinterpret_cast<float4*>(sT2 + i * STRD + (c - 64) * 4) = v;
        }
        const float4* f2v = reinterpret_cast<const float4*>(F2 + (size_t)b * NN * DD);
        #pragma unroll
        for (int i4 = t; i4 < NN * 64; i4 += 128) {
            int k = i4 >> 6, d4 = i4 & 63;
            *reinterpret_cast<float4*>(sF + k * STRD + d4 * 4) = f2v[i4];
        }
    }
    __syncthreads();

    // ---- P and Q, 2x2 (i,k) tiles, both matrices per thread ----
    if (t < 100) {
        const int i0 = (t / 10) * 2;
        const int k0 = (t - (t / 10) * 10) * 2;
        const ulonglong2* T1a = reinterpret_cast<const ulonglong2*>(sT1 + i0 * STRD);
        const ulonglong2* T1b = reinterpret_cast<const ulonglong2*>(sT1 + (i0 + 1) * STRD);
        const ulonglong2* T2a = reinterpret_cast<const ulonglong2*>(sT2 + i0 * STRD);
        const ulonglong2* T2b = reinterpret_cast<const ulonglong2*>(sT2 + (i0 + 1) * STRD);
        const ulonglong2* Fa  = reinterpret_cast<const ulonglong2*>(sF + k0 * STRD);
        const ulonglong2* Fb  = reinterpret_cast<const ulonglong2*>(sF + (k0 + 1) * STRD);

        ull p00 = 0, p01 = 0, p10 = 0, p11 = 0;
        ull q00 = 0, q01 = 0, q10 = 0, q11 = 0;
        #pragma unroll 4
        for (int v = 0; v < DD / 4; v++) {
            ulonglong2 t1a = T1a[v], t1b = T1b[v];
            ulonglong2 t2a = T2a[v], t2b = T2b[v];
            ulonglong2 fa  = Fa[v],  fb  = Fb[v];
            FMA2(p00, t1a.x, fa.x); FMA2(p00, t1a.y, fa.y);
            FMA2(p01, t1a.x, fb.x); FMA2(p01, t1a.y, fb.y);
            FMA2(p10, t1b.x, fa.x); FMA2(p10, t1b.y, fa.y);
            FMA2(p11, t1b.x, fb.x); FMA2(p11, t1b.y, fb.y);
            FMA2(q00, t2a.x, fa.x); FMA2(q00, t2a.y, fa.y);
            FMA2(q01, t2a.x, fb.x); FMA2(q01, t2a.y, fb.y);
            FMA2(q10, t2b.x, fa.x); FMA2(q10, t2b.y, fa.y);
            FMA2(q11, t2b.x, fb.x); FMA2(q11, t2b.y, fb.y);
        }
        float* dst = g_scratch + b * 1200;
        dst[i0 * NN + k0]             = red64(p00);
        dst[i0 * NN + k0 + 1]         = red64(p01);
        dst[(i0 + 1) * NN + k0]       = red64(p10);
        dst[(i0 + 1) * NN + k0 + 1]   = red64(p11);
        dst += 400;
        dst[i0 * NN + k0]             = red64(q00);
        dst[i0 * NN + k0 + 1]         = red64(q01);
        dst[(i0 + 1) * NN + k0]       = red64(q10);
        dst[(i0 + 1) * NN + k0 + 1]   = red64(q11);
    }
    __syncthreads();

    // ---- restage: U1 -> sT1, U2 -> sF ----
    {
        const float4* u1v = reinterpret_cast<const float4*>(U1 + (size_t)b * NN * DD);
        const float4* u2v = reinterpret_cast<const float4*>(U2 + (size_t)b * NN * DD);
        #pragma unroll
        for (int i4 = t; i4 < NN * 64; i4 += 128) {
            int k = i4 >> 6, d4 = i4 & 63;
            *reinterpret_cast<float4*>(sT1 + k * STRD + d4 * 4) = u1v[i4];
            *reinterpret_cast<float4*>(sF  + k * STRD + d4 * 4) = u2v[i4];
        }
    }
    __syncthreads();

    // ---- Mn, 2x2 tiles ----
    if (t < 100) {
        const int i0 = (t / 10) * 2;
        const int k0 = (t - (t / 10) * 10) * 2;
        const ulonglong2* Ua = reinterpret_cast<const ulonglong2*>(sT1 + i0 * STRD);
        const ulonglong2* Ub = reinterpret_cast<const ulonglong2*>(sT1 + (i0 + 1) * STRD);
        const ulonglong2* Ka = reinterpret_cast<const ulonglong2*>(sF + k0 * STRD);
        const ulonglong2* Kb = reinterpret_cast<const ulonglong2*>(sF + (k0 + 1) * STRD);

        ull m00 = 0, m01 = 0, m10 = 0, m11 = 0;
        #pragma unroll 4
        for (int v = 0; v < DD / 4; v++) {
            ulonglong2 ua = Ua[v], ub = Ub[v];
            ulonglong2 ka = Ka[v], kb = Kb[v];
            FMA2(m00, ua.x, ka.x); FMA2(m00, ua.y, ka.y);
            FMA2(m01, ua.x, kb.x); FMA2(m01, ua.y, kb.y);
            FMA2(m10, ub.x, ka.x); FMA2(m10, ub.y, ka.y);
            FMA2(m11, ub.x, kb.x); FMA2(m11, ub.y, kb.y);
        }
        float* dstM = g_scratch + b * 1200 + 800;
        dstM[i0 * NN + k0]           = red64(m00);
        dstM[i0 * NN + k0 + 1]       = red64(m01);
        dstM[(i0 + 1) * NN + k0]     = red64(m10);
        dstM[(i0 + 1) * NN + k0 + 1] = red64(m11);
    }
}

// ------------------------------------------------------------------ write ---
__global__ void __launch_bounds__(512)
write_kernel(float* __restrict__ out)
{
    __shared__ __align__(16) float sPT[NN * 24];
    __shared__ __align__(16) float sQT[NN * 24];
    __shared__ float sPd[NN * 21];
    __shared__ float sQd[NN * 21];
    __shared__ float sMnD[NN * 21];

    const int h = blockIdx.x;
    const int b = blockIdx.y;
    const int t = threadIdx.x;

    const float* s = g_scratch + (size_t)b * 1200;

    if (t < 400) {
        int i = t / NN, k = t - i * NN;
        float pv = s[t], qv = s[400 + t], mv = s[800 + t];
        sPd[i * 21 + k] = pv;
        sPT[k * 24 + i] = pv;
        sQd[i * 21 + k] = qv;
        sQT[k * 24 + i] = qv;
        sMnD[i * 21 + k] = mv;
    }
    __syncthreads();

    if (t < 500) {
        const int x0 = t / 100;
        const int cm = t - x0 * 100;
        const int q  = cm / 5;
        const int y0 = (cm - q * 5) * 4;

        const float4 pt = *reinterpret_cast<const float4*>(sPT + q * 24 + y0);
        int   xs[4];
        float c2[4];
        int   dxv[4];
        #pragma unroll
        for (int j = 0; j < 4; j++) {
            xs[j]  = x0 + 5 * j;
            c2[j]  = sQd[xs[j] * 21 + q];
            dxv[j] = xs[j] - y0;
        }

        float4* ob = reinterpret_cast<float4*>(out) + (size_t)b * 40000 + cm;

        #pragma unroll 2
        for (int pp = 0; pp < 10; pp++) {
            const int p = h * 10 + pp;
            const float4 qc = *reinterpret_cast<const float4*>(sQT + p * 24 + y0);
            const float bx = pt.x + qc.x, by = pt.y + qc.y;
            const float bz = pt.z + qc.z, bw = pt.w + qc.w;
            float4* obp = ob + p * 2000;

            if (q != p) {
                #pragma unroll
                for (int j = 0; j < 4; j++) {
                    const int x = xs[j];
                    const float c1 = sPd[x * 21 + p] + c2[j];
                    float4 v = make_float4(c1 + bx, c1 + by, c1 + bz, c1 + bw);
                    const int dx = dxv[j];
                    if (dx == 0) v.x = 0.f;
                    else if (dx == 1) v.y = 0.f;
                    else if (dx == 2) v.z = 0.f;
                    else if (dx == 3) v.w = 0.f;
                    __stcs(&obp[x * 100], v);
                }
            } else {
                #pragma unroll
                for (int j = 0; j < 4; j++) {
                    const int x = xs[j];
                    float4 v = make_float4(0.f, 0.f, 0.f, 0.f);
                    const float mn = sMnD[x * 21 + p];
                    const int dx = dxv[j];
                    if (dx == 0) v.x = mn;
                    else if (dx == 1) v.y = mn;
                    else if (dx == 2) v.z = mn;
                    else if (dx == 3) v.w = mn;
                    __stcs(&obp[x * 100], v);
                }
            }
        }
    }
}

// ----------------------------------------------------------------- launch ---
extern "C" void kernel_launch(void* const* d_in, const int* in_sizes, int n_in,
                              void* d_out, int out_size)
{
    const float* Fs[4] = {nullptr, nullptr, nullptr, nullptr};
    const float* Ls[2] = {nullptr, nullptr};
    int nf = 0, nl = 0;
    for (int i = 0; i < n_in; i++) {
        if (in_sizes[i] == NB * NN * DD) {
            if (nf < 4) Fs[nf++] = (const float*)d_in[i];
        } else if (in_sizes[i] == DD * DD) {
            if (nl < 2) Ls[nl++] = (const float*)d_in[i];
        }
    }

    cudaFuncSetAttribute(pq_kernel,
                         cudaFuncAttributeMaxDynamicSharedMemorySize, PQ_SMEM_BYTES);

    const int prep_threads = MB16 * KB16 * 32 + NB16 * KB16 * 32;  // 180224
    prep_kernel<<<prep_threads / 256, 256>>>(Fs[0], Ls[0], Ls[1]);
    gemm_kernel<<<dim3(8, 40), 256>>>();
    pq_kernel<<<NB, 128, PQ_SMEM_BYTES>>>(Fs[1], Fs[2], Fs[3]);
    write_kernel<<<dim3(2, NB), 512>>>((float*)d_out);
    (void)out_size;
}